// round 16
// baseline (speedup 1.0000x reference)
#include <cuda_runtime.h>
#include <cuda_fp16.h>

#define EMB 32
#define K 10
#define APITCH 72       // halves per A row (144B): ldmatrix conflict-free, 16B-aligned rows
#define WPITCH 72       // halves per Whs row
#define NPB 64          // nodes per block (16 per warp)
#define SPITCH 42       // uint4 chunks per staged node (672B)

// fp16 tables (device globals: allocation-free scratch)
__device__ __align__(16) __half g_embh[500000 * EMB];   // 32 MB
__device__ __align__(16) __half g_h1h [500000 * EMB];   // 32 MB

// unpack 8 halves (one uint4) -> 8 floats
__device__ __forceinline__ void cvt8(uint4 v, float* f)
{
    const __half2* h = reinterpret_cast<const __half2*>(&v);
    #pragma unroll
    for (int i = 0; i < 4; i++) {
        float2 t = __half22float2(h[i]);
        f[2 * i]     = t.x;
        f[2 * i + 1] = t.y;
    }
}

__device__ __forceinline__ void cp_async16(unsigned saddr, const void* gptr)
{
    asm volatile("cp.async.cg.shared.global [%0], [%1], 16;"
                 :: "r"(saddr), "l"(gptr));
}

// ---- fp32 -> fp16 conversion; evict-first loads (single-use stream) ----
__global__ __launch_bounds__(256)
void cvt_f32_to_f16(const float4* __restrict__ src, uint4* __restrict__ dst, int n8)
{
    int i = blockIdx.x * blockDim.x + threadIdx.x;
    int stride = gridDim.x * blockDim.x;
    for (; i < n8; i += stride) {
        float4 a, b;
        asm volatile("ld.global.cs.v4.f32 {%0,%1,%2,%3}, [%4];"
                     : "=f"(a.x), "=f"(a.y), "=f"(a.z), "=f"(a.w)
                     : "l"(src + 2 * i));
        asm volatile("ld.global.cs.v4.f32 {%0,%1,%2,%3}, [%4];"
                     : "=f"(b.x), "=f"(b.y), "=f"(b.z), "=f"(b.w)
                     : "l"(src + 2 * i + 1));
        __half2 h[4];
        h[0] = __floats2half2_rn(a.x, a.y); h[1] = __floats2half2_rn(a.z, a.w);
        h[2] = __floats2half2_rn(b.x, b.y); h[3] = __floats2half2_rn(b.z, b.w);
        dst[i] = *reinterpret_cast<const uint4*>(h);
    }
}

// ======================================================================
// FUSED layer kernel: hybrid gather — pass1 via cp.async (smem staged),
// pass0 via register LDGs; both passes in flight. HMMA m16n8k16 tail.
// ======================================================================
__device__ __forceinline__ void mma16816(float* c, const unsigned* a,
                                         unsigned b0, unsigned b1)
{
    asm volatile(
        "mma.sync.aligned.m16n8k16.row.col.f32.f16.f16.f32 "
        "{%0,%1,%2,%3}, {%4,%5,%6,%7}, {%8,%9}, {%0,%1,%2,%3};"
        : "+f"(c[0]), "+f"(c[1]), "+f"(c[2]), "+f"(c[3])
        : "r"(a[0]), "r"(a[1]), "r"(a[2]), "r"(a[3]), "r"(b0), "r"(b1));
}

__device__ __forceinline__ void ldsm_x4(unsigned* r, unsigned addr)
{
    asm volatile(
        "ldmatrix.sync.aligned.m8n8.x4.shared.b16 {%0,%1,%2,%3}, [%4];"
        : "=r"(r[0]), "=r"(r[1]), "=r"(r[2]), "=r"(r[3]) : "r"(addr));
}

template<bool SELF_GATHER, bool OUT_HALF>
__global__ __launch_bounds__(128, 6)
void sage_fused_kernel(const __half* __restrict__ feat,      // [*, 32] fp16
                       const int*    __restrict__ node_ids,  // if SELF_GATHER
                       const int*    __restrict__ neigh,     // [N_NODES, K]
                       const float*  __restrict__ W,         // [32 out, 64 in]
                       void*         __restrict__ outp,
                       int n)
{
    __shared__ __align__(16) __half As[NPB * APITCH];     // 9.2 KB
    __shared__ __align__(16) __half Whs[32 * WPITCH];     // 4.6 KB
    __shared__ __align__(16) uint4  Stg[32 * SPITCH];     // 21.5 KB (pass-1 only)

    const int tid   = threadIdx.x;
    const int lane  = tid & 31;
    const int wrp   = tid >> 5;
    const int g     = lane >> 2;      // node-group 0..7
    const int tig   = lane & 3;       // 16B chunk within 64B row
    const int nbase = blockIdx.x * NPB + wrp * 16;

    // ---- stage W (fp32 -> fp16) into smem ----
    #pragma unroll
    for (int e = tid * 2; e < 32 * 64; e += 256) {
        int nr = e >> 6, kc = e & 63;
        __half2 h = __floats2half2_rn(W[e], W[e + 1]);
        *reinterpret_cast<__half2*>(&Whs[nr * WPITCH + kc]) = h;
    }
    __syncthreads();   // only block-wide barrier

    const int r0 = wrp * 16 + g, r1 = r0 + 8;   // block-local As rows
    const int sg = wrp * 8 + g;                 // this thread-group's stage slot
    int t0  = nbase + g,       t1 = nbase + 8 + g;
    int tc0 = min(t0, n - 1),  tc1 = min(t1, n - 1);
    int sid0 = SELF_GATHER ? node_ids[tc0] : tc0;
    int sid1 = SELF_GATHER ? node_ids[tc1] : tc1;

    unsigned asb = (unsigned)__cvta_generic_to_shared(As);
    unsigned stb = (unsigned)__cvta_generic_to_shared(Stg);

    // ---- PASS 1 first: 11 cp.asyncs (ids consumed immediately, no reg hold) ----
    {
        int nb1[K];
        #pragma unroll
        for (int k = 0; k < K; k++) nb1[k] = neigh[sid1 * K + k];
        cp_async16(asb + (r1 * APITCH + tig * 8) * 2,
                   feat + (size_t)sid1 * EMB + tig * 8);          // self1 -> As
        #pragma unroll
        for (int k = 0; k < K; k++)
            cp_async16(stb + (sg * SPITCH + k * 4 + tig) * 16,
                       feat + (size_t)nb1[k] * EMB + tig * 8);    // neigh1 -> Stg
        asm volatile("cp.async.commit_group;");
    }

    // ---- PASS 0: register LDGs (in flight concurrently with pass 1) ----
    uint4 vs0;
    uint4 raw[K];
    {
        int nb0[K];
        #pragma unroll
        for (int k = 0; k < K; k++) nb0[k] = neigh[sid0 * K + k];
        vs0 = *(reinterpret_cast<const uint4*>(feat + (size_t)sid0 * EMB) + tig);
        #pragma unroll
        for (int k = 0; k < K; k++)
            raw[k] = *(reinterpret_cast<const uint4*>(feat + (size_t)nb0[k] * EMB) + tig);
    }

    // ---- sum pass 0 ----
    {
        float acc[8] = {0,0,0,0,0,0,0,0};
        #pragma unroll
        for (int k = 0; k < K; k++) {
            float f[8]; cvt8(raw[k], f);
            #pragma unroll
            for (int i = 0; i < 8; i++) acc[i] += f[i];
        }
        __half2 h[4];
        #pragma unroll
        for (int i = 0; i < 4; i++)
            h[i] = __floats2half2_rn(acc[2 * i] * 0.1f, acc[2 * i + 1] * 0.1f);
        __half* dst = &As[r0 * APITCH];
        *reinterpret_cast<uint4*>(dst + tig * 8)      = vs0;
        *reinterpret_cast<uint4*>(dst + 32 + tig * 8) = *reinterpret_cast<const uint4*>(h);
    }

    // ---- pass 1 should be complete by now; sum from stage ----
    asm volatile("cp.async.wait_group 0;" ::: "memory");
    {
        float acc[8] = {0,0,0,0,0,0,0,0};
        #pragma unroll
        for (int k = 0; k < K; k++) {
            float f[8]; cvt8(Stg[sg * SPITCH + k * 4 + tig], f);
            #pragma unroll
            for (int i = 0; i < 8; i++) acc[i] += f[i];
        }
        __half2 h[4];
        #pragma unroll
        for (int i = 0; i < 4; i++)
            h[i] = __floats2half2_rn(acc[2 * i] * 0.1f, acc[2 * i + 1] * 0.1f);
        *reinterpret_cast<uint4*>(&As[r1 * APITCH + 32 + tig * 8])
            = *reinterpret_cast<const uint4*>(h);
    }
    __syncwarp();   // As tile complete for this warp

    // ---- mma mainloop (1 m-tile x 4 n-tiles x 4 k-tiles) ----
    float acc[4][4];
    #pragma unroll
    for (int nt = 0; nt < 4; nt++)
        #pragma unroll
        for (int q = 0; q < 4; q++) acc[nt][q] = 0.f;

    #pragma unroll
    for (int kt = 0; kt < 4; kt++) {
        unsigned bfr[8];
        #pragma unroll
        for (int hgrp = 0; hgrp < 2; hgrp++) {
            int tl   = lane >> 3;
            int rr   = lane & 7;
            int nrow = hgrp * 16 + (tl >> 1) * 8 + rr;
            int kcol = kt * 16 + (tl & 1) * 8;
            unsigned addr = (unsigned)__cvta_generic_to_shared(
                                &Whs[nrow * WPITCH + kcol]);
            ldsm_x4(&bfr[4 * hgrp], addr);
        }
        int row  = wrp * 16 + (lane & 15);
        int colh = kt * 16 + (lane >> 4) * 8;
        unsigned addr = (unsigned)__cvta_generic_to_shared(
                            &As[row * APITCH + colh]);
        unsigned a[4];
        ldsm_x4(a, addr);
        #pragma unroll
        for (int nt = 0; nt < 4; nt++)
            mma16816(acc[nt], a, bfr[2 * nt], bfr[2 * nt + 1]);
    }

    // ---- relu + store ----
    #pragma unroll
    for (int nt = 0; nt < 4; nt++) {
        int rr0 = nbase + g;
        int rr1 = rr0 + 8;
        int col = nt * 8 + tig * 2;
        float c0  = fmaxf(acc[nt][0], 0.f);
        float c1  = fmaxf(acc[nt][1], 0.f);
        float c2v = fmaxf(acc[nt][2], 0.f);
        float c3v = fmaxf(acc[nt][3], 0.f);
        if (OUT_HALF) {
            __half* out = reinterpret_cast<__half*>(outp);
            if (rr0 < n)
                *reinterpret_cast<__half2*>(out + (size_t)rr0 * EMB + col)
                    = __floats2half2_rn(c0, c1);
            if (rr1 < n)
                *reinterpret_cast<__half2*>(out + (size_t)rr1 * EMB + col)
                    = __floats2half2_rn(c2v, c3v);
        } else {
            float* out = reinterpret_cast<float*>(outp);
            if (rr0 < n)
                asm volatile("st.global.cs.v2.f32 [%0], {%1,%2};"
                             :: "l"(out + (size_t)rr0 * EMB + col), "f"(c0), "f"(c1)
                             : "memory");
            if (rr1 < n)
                asm volatile("st.global.cs.v2.f32 [%0], {%1,%2};"
                             :: "l"(out + (size_t)rr1 * EMB + col), "f"(c2v), "f"(c3v)
                             : "memory");
        }
    }
}

extern "C" void kernel_launch(void* const* d_in, const int* in_sizes, int n_in,
                              void* d_out, int out_size)
{
    // metadata order: emb, W1, W2, node_batch, neigh
    const float* emb        = (const float*)d_in[0];
    const float* W1         = (const float*)d_in[1];
    const float* W2         = (const float*)d_in[2];
    const int*   node_batch = (const int*)  d_in[3];
    const int*   neigh      = (const int*)  d_in[4];
    float*       out        = (float*)d_out;

    const int N = in_sizes[0] / EMB;   // 500000
    const int B = in_sizes[3];         // 100000

    __half *embh = nullptr, *h1h = nullptr;
    cudaGetSymbolAddress((void**)&embh, g_embh);
    cudaGetSymbolAddress((void**)&h1h,  g_h1h);

    // emb fp32 -> fp16 (keeps gather working set L2-resident)
    cvt_f32_to_f16<<<8192, 256>>>((const float4*)emb, (uint4*)embh, N * EMB / 8);

    // Layer 1: h1 = relu([emb | mean(emb[neigh])] @ W1^T)  (fused, fp16 out)
    sage_fused_kernel<false, true><<<(N + NPB - 1) / NPB, 128>>>(
        embh, nullptr, neigh, W1, h1h, N);

    // Layer 2: out = relu([h1[nb] | mean(h1[neigh[nb]])] @ W2^T)  (fused, fp32 out)
    sage_fused_kernel<true, false><<<(B + NPB - 1) / NPB, 128>>>(
        h1h, node_batch, neigh, W2, out, B);
}

// round 17
// speedup vs baseline: 1.0882x; 1.0882x over previous
#include <cuda_runtime.h>
#include <cuda_fp16.h>

#define EMB 32
#define K 10
#define APITCH 72       // halves per A row (144B): ldmatrix conflict-free
#define WPITCH 72       // halves per Whs row
#define NPB 32          // nodes per block (8 per warp, 4 warps)

// fp16 tables (device globals: allocation-free scratch)
__device__ __align__(16) __half g_embh[500000 * EMB];   // 32 MB
__device__ __align__(16) __half g_h1h [500000 * EMB];   // 32 MB

// unpack 8 halves (one uint4) -> 8 floats
__device__ __forceinline__ void cvt8(uint4 v, float* f)
{
    const __half2* h = reinterpret_cast<const __half2*>(&v);
    #pragma unroll
    for (int i = 0; i < 4; i++) {
        float2 t = __half22float2(h[i]);
        f[2 * i]     = t.x;
        f[2 * i + 1] = t.y;
    }
}

// ---- fp32 -> fp16 conversion; evict-first loads (single-use stream) ----
__global__ __launch_bounds__(256)
void cvt_f32_to_f16(const float4* __restrict__ src, uint4* __restrict__ dst, int n8)
{
    int i = blockIdx.x * blockDim.x + threadIdx.x;
    int stride = gridDim.x * blockDim.x;
    for (; i < n8; i += stride) {
        float4 a, b;
        asm volatile("ld.global.cs.v4.f32 {%0,%1,%2,%3}, [%4];"
                     : "=f"(a.x), "=f"(a.y), "=f"(a.z), "=f"(a.w)
                     : "l"(src + 2 * i));
        asm volatile("ld.global.cs.v4.f32 {%0,%1,%2,%3}, [%4];"
                     : "=f"(b.x), "=f"(b.y), "=f"(b.z), "=f"(b.w)
                     : "l"(src + 2 * i + 1));
        __half2 h[4];
        h[0] = __floats2half2_rn(a.x, a.y); h[1] = __floats2half2_rn(a.z, a.w);
        h[2] = __floats2half2_rn(b.x, b.y); h[3] = __floats2half2_rn(b.z, b.w);
        dst[i] = *reinterpret_cast<const uint4*>(h);
    }
}

// ======================================================================
// FUSED layer kernel: 8 nodes/warp (ONE gather pass), warp-paired MMA.
// Pair p = warps {2p, 2p+1} share a 16-row A tile; each warp computes
// 2 of the 4 n-tiles.  HMMA m16n8k16.
// ======================================================================
__device__ __forceinline__ void mma16816(float* c, const unsigned* a,
                                         unsigned b0, unsigned b1)
{
    asm volatile(
        "mma.sync.aligned.m16n8k16.row.col.f32.f16.f16.f32 "
        "{%0,%1,%2,%3}, {%4,%5,%6,%7}, {%8,%9}, {%0,%1,%2,%3};"
        : "+f"(c[0]), "+f"(c[1]), "+f"(c[2]), "+f"(c[3])
        : "r"(a[0]), "r"(a[1]), "r"(a[2]), "r"(a[3]), "r"(b0), "r"(b1));
}

__device__ __forceinline__ void ldsm_x4(unsigned* r, unsigned addr)
{
    asm volatile(
        "ldmatrix.sync.aligned.m8n8.x4.shared.b16 {%0,%1,%2,%3}, [%4];"
        : "=r"(r[0]), "=r"(r[1]), "=r"(r[2]), "=r"(r[3]) : "r"(addr));
}

template<bool SELF_GATHER, bool OUT_HALF>
__global__ __launch_bounds__(128, 8)
void sage_fused_kernel(const __half* __restrict__ feat,      // [*, 32] fp16
                       const int*    __restrict__ node_ids,  // if SELF_GATHER
                       const int*    __restrict__ neigh,     // [N_NODES, K]
                       const float*  __restrict__ W,         // [32 out, 64 in]
                       void*         __restrict__ outp,
                       int n)
{
    __shared__ __align__(16) __half As[NPB * APITCH];     // 4.6 KB
    __shared__ __align__(16) __half Whs[32 * WPITCH];     // 4.6 KB

    const int tid   = threadIdx.x;
    const int lane  = tid & 31;
    const int wrp   = tid >> 5;
    const int g     = lane >> 2;      // node-group 0..7
    const int tig   = lane & 3;       // 16B chunk within 64B row
    const int bbase = blockIdx.x * NPB;

    // ---- stage W (fp32 -> fp16) into smem ----
    #pragma unroll
    for (int e = tid * 2; e < 32 * 64; e += 256) {
        int nr = e >> 6, kc = e & 63;
        __half2 h = __floats2half2_rn(W[e], W[e + 1]);
        *reinterpret_cast<__half2*>(&Whs[nr * WPITCH + kc]) = h;
    }

    // ---- ONE gather pass: this thread's node ----
    const int row = wrp * 8 + g;              // block-local As row
    int t   = bbase + row;
    int tc  = min(t, n - 1);
    int sid = SELF_GATHER ? node_ids[tc] : tc;

    int nb[K];                                // group-uniform (L1 broadcast)
    #pragma unroll
    for (int k = 0; k < K; k++) nb[k] = neigh[sid * K + k];

    uint4 vs = *(reinterpret_cast<const uint4*>(feat + (size_t)sid * EMB) + tig);
    uint4 raw[K];                             // 10 independent LDG.128 in flight
    #pragma unroll
    for (int k = 0; k < K; k++)
        raw[k] = *(reinterpret_cast<const uint4*>(feat + (size_t)nb[k] * EMB) + tig);

    float acc8[8] = {0,0,0,0,0,0,0,0};
    #pragma unroll
    for (int k = 0; k < K; k++) {
        float f[8]; cvt8(raw[k], f);
        #pragma unroll
        for (int i = 0; i < 8; i++) acc8[i] += f[i];
    }
    {
        __half2 h[4];
        #pragma unroll
        for (int i = 0; i < 4; i++)
            h[i] = __floats2half2_rn(acc8[2 * i] * 0.1f, acc8[2 * i + 1] * 0.1f);
        __half* dst = &As[row * APITCH];
        *reinterpret_cast<uint4*>(dst + tig * 8)      = vs;
        *reinterpret_cast<uint4*>(dst + 32 + tig * 8) = *reinterpret_cast<const uint4*>(h);
    }
    __syncthreads();    // Whs + all four warps' As rows ready

    // ---- warp-paired MMA: pair p shares rows [p*16, p*16+16) ----
    const int p   = wrp >> 1;
    const int hnt = wrp & 1;          // this warp's n-tile half (0: cols 0-15, 1: 16-31)

    float acc[2][4];
    #pragma unroll
    for (int nt = 0; nt < 2; nt++)
        #pragma unroll
        for (int q = 0; q < 4; q++) acc[nt][q] = 0.f;

    #pragma unroll
    for (int kt = 0; kt < 4; kt++) {
        // B frags for this warp's 2 n-tiles: one ldmatrix.x4
        unsigned bfr[4];
        {
            int tl   = lane >> 3;
            int rr   = lane & 7;
            int nrow = hnt * 16 + (tl >> 1) * 8 + rr;
            int kcol = kt * 16 + (tl & 1) * 8;
            unsigned addr = (unsigned)__cvta_generic_to_shared(
                                &Whs[nrow * WPITCH + kcol]);
            ldsm_x4(bfr, addr);
        }
        // A frag for the pair's 16 rows
        int arow = p * 16 + (lane & 15);
        int colh = kt * 16 + (lane >> 4) * 8;
        unsigned addr = (unsigned)__cvta_generic_to_shared(
                            &As[arow * APITCH + colh]);
        unsigned a[4];
        ldsm_x4(a, addr);
        #pragma unroll
        for (int nt = 0; nt < 2; nt++)
            mma16816(acc[nt], a, bfr[2 * nt], bfr[2 * nt + 1]);
    }

    // ---- relu + store: warp writes its 2 n-tiles of the pair's 16 rows ----
    #pragma unroll
    for (int nt = 0; nt < 2; nt++) {
        int r0  = bbase + p * 16 + g;
        int r1  = r0 + 8;
        int col = (hnt * 2 + nt) * 8 + tig * 2;
        float c0  = fmaxf(acc[nt][0], 0.f);
        float c1  = fmaxf(acc[nt][1], 0.f);
        float c2v = fmaxf(acc[nt][2], 0.f);
        float c3v = fmaxf(acc[nt][3], 0.f);
        if (OUT_HALF) {
            __half* out = reinterpret_cast<__half*>(outp);
            if (r0 < n)
                *reinterpret_cast<__half2*>(out + (size_t)r0 * EMB + col)
                    = __floats2half2_rn(c0, c1);
            if (r1 < n)
                *reinterpret_cast<__half2*>(out + (size_t)r1 * EMB + col)
                    = __floats2half2_rn(c2v, c3v);
        } else {
            float* out = reinterpret_cast<float*>(outp);
            if (r0 < n)
                asm volatile("st.global.cs.v2.f32 [%0], {%1,%2};"
                             :: "l"(out + (size_t)r0 * EMB + col), "f"(c0), "f"(c1)
                             : "memory");
            if (r1 < n)
                asm volatile("st.global.cs.v2.f32 [%0], {%1,%2};"
                             :: "l"(out + (size_t)r1 * EMB + col), "f"(c2v), "f"(c3v)
                             : "memory");
        }
    }
}

extern "C" void kernel_launch(void* const* d_in, const int* in_sizes, int n_in,
                              void* d_out, int out_size)
{
    // metadata order: emb, W1, W2, node_batch, neigh
    const float* emb        = (const float*)d_in[0];
    const float* W1         = (const float*)d_in[1];
    const float* W2         = (const float*)d_in[2];
    const int*   node_batch = (const int*)  d_in[3];
    const int*   neigh      = (const int*)  d_in[4];
    float*       out        = (float*)d_out;

    const int N = in_sizes[0] / EMB;   // 500000
    const int B = in_sizes[3];         // 100000

    __half *embh = nullptr, *h1h = nullptr;
    cudaGetSymbolAddress((void**)&embh, g_embh);
    cudaGetSymbolAddress((void**)&h1h,  g_h1h);

    // emb fp32 -> fp16 (keeps gather working set L2-resident)
    cvt_f32_to_f16<<<8192, 256>>>((const float4*)emb, (uint4*)embh, N * EMB / 8);

    // Layer 1: h1 = relu([emb | mean(emb[neigh])] @ W1^T)  (fused, fp16 out)
    sage_fused_kernel<false, true><<<(N + NPB - 1) / NPB, 128>>>(
        embh, nullptr, neigh, W1, h1h, N);

    // Layer 2: out = relu([h1[nb] | mean(h1[neigh[nb]])] @ W2^T)  (fused, fp32 out)
    sage_fused_kernel<true, false><<<(B + NPB - 1) / NPB, 128>>>(
        h1h, node_batch, neigh, W2, out, B);
}